// round 13
// baseline (speedup 1.0000x reference)
#include <cuda_runtime.h>
#include <cuda_fp16.h>
#include <cstdint>

#define B_  16
#define N_  512
#define T_  64
#define OC_ 64

// ---------------- scratch (device globals; no runtime allocation) ----------
__device__ __align__(16) float  g_norm  [N_ * N_];      // fp32 (k_norm2 input)
__device__ __align__(16) __half g_normh [N_ * N_];      // fp16 (spmm A)
__device__ __align__(16) __half g_norm2h[N_ * N_];      // fp16 (spmm A)
__device__ __align__(16) __half g_Z1h[B_ * OC_ * N_ * T_];
__device__ __align__(16) __half g_Z2h[B_ * OC_ * N_ * T_];
__device__ __align__(16) __half g_Whf[192 * 64];        // [gc][c] fp16

// ======================= helpers ===========================================
__device__ __forceinline__ uint32_t smem_u32(const void* p) {
    uint32_t a;
    asm("{ .reg .u64 t; cvta.to.shared.u64 t, %1; cvt.u32.u64 %0, t; }"
        : "=r"(a) : "l"(p));
    return a;
}

#define CP16(dst, src) \
    asm volatile("cp.async.cg.shared.global [%0], [%1], 16;" \
                 :: "r"(dst), "l"(src) : "memory")
#define CP_COMMIT()  asm volatile("cp.async.commit_group;" ::: "memory")
#define CP_WAIT1()   asm volatile("cp.async.wait_group 1;" ::: "memory")
#define CP_WAIT0()   asm volatile("cp.async.wait_group 0;" ::: "memory")

#define MMA_F16(c, a0, a1, a2, a3, b0, b1) \
    asm volatile("mma.sync.aligned.m16n8k16.row.col.f32.f16.f16.f32 " \
                 "{%0,%1,%2,%3}, {%4,%5,%6,%7}, {%8,%9}, {%0,%1,%2,%3};" \
                 : "+f"((c)[0]), "+f"((c)[1]), "+f"((c)[2]), "+f"((c)[3]) \
                 : "r"(a0), "r"(a1), "r"(a2), "r"(a3), "r"(b0), "r"(b1))

__device__ __forceinline__ void ldsm_x4(uint32_t* r, uint32_t addr) {
    asm volatile("ldmatrix.sync.aligned.m8n8.x4.shared.b16 {%0,%1,%2,%3}, [%4];"
                 : "=r"(r[0]), "=r"(r[1]), "=r"(r[2]), "=r"(r[3]) : "r"(addr));
}
__device__ __forceinline__ void ldsm_x4t(uint32_t* r, uint32_t addr) {
    asm volatile("ldmatrix.sync.aligned.m8n8.x4.trans.shared.b16 {%0,%1,%2,%3}, [%4];"
                 : "=r"(r[0]), "=r"(r[1]), "=r"(r[2]), "=r"(r[3]) : "r"(addr));
}

// ---------------- kernel 0a: row-normalized adjacency (+ fused W convert) --
__global__ void k_rownorm(const float* __restrict__ adj,
                          const float* __restrict__ W) {
    const int i = blockIdx.x;
    __shared__ float red[256];
    float s = 0.f;
    for (int j = threadIdx.x; j < N_; j += 256) s += adj[i * N_ + j];
    red[threadIdx.x] = s;
    __syncthreads();
    for (int off = 128; off > 0; off >>= 1) {
        if (threadIdx.x < off) red[threadIdx.x] += red[threadIdx.x + off];
        __syncthreads();
    }
    const float inv = 1.0f / (red[0] + 1e-6f);
    for (int j = threadIdx.x; j < N_; j += 256) {
        const float v = adj[i * N_ + j] * inv;
        g_norm [i * N_ + j] = v;
        g_normh[i * N_ + j] = __float2half_rn(v);
    }
    // fused W -> fp16 [gc][c]: blocks 0..47 cover 192*64 = 48*256 elements
    if (i < 48) {
        const int idx = i * 256 + threadIdx.x;      // idx = gc*64 + c
        const int gc = idx >> 6, c = idx & 63;
        const int grp = gc >> 6, oc = gc & 63;
        g_Whf[idx] = __float2half_rn(W[oc * 192 + grp * 64 + c]);
    }
}

// ---------------- kernel 0b: norm2 = norm @ norm (fp16 store) --------------
__global__ void k_norm2() {
    __shared__ float As[16][16];
    __shared__ float Bs[16][17];
    const int i = blockIdx.y * 16 + threadIdx.y;
    const int j = blockIdx.x * 16 + threadIdx.x;
    float acc = 0.f;
    for (int k0 = 0; k0 < N_; k0 += 16) {
        As[threadIdx.y][threadIdx.x] = g_norm[i * N_ + k0 + threadIdx.x];
        Bs[threadIdx.y][threadIdx.x] = g_norm[(k0 + threadIdx.y) * N_ + j];
        __syncthreads();
#pragma unroll
        for (int k = 0; k < 16; k++) acc += As[threadIdx.y][k] * Bs[k][threadIdx.x];
        __syncthreads();
    }
    g_norm2h[i * N_ + j] = __float2half_rn(acc);
}

// ---------------- kernel 1: channel mix via fp16 tensor cores ---------------
// CTA = (n4, cn, b). GEMM: M=256 (4n x 64t), N=96 (cn half of 192), K=64.
// Xh smem [c][m] (A via ldmatrix.trans); Wh [gc'][c] (B non-trans).
// Single-pass epilogue: all 96 output cols staged in one Ss (99840B smem).
#define XHST 264
#define WHST 72
#define SST  260
#define MIX_SMEM 99840                         // Ss 96*260*4 (reuses X+W region)

__global__ __launch_bounds__(256, 2) void k_mix_f16(const float* __restrict__ x,
                                                    const float* __restrict__ bias,
                                                    float* __restrict__ out) {
    extern __shared__ char dsm[];
    __half* Xh = (__half*)dsm;                       // [c=64][m=256]
    const uint32_t sb = smem_u32(dsm);
    const uint32_t wOff = 64 * XHST * 2;             // 33792
    const int n0 = blockIdx.x * 4, cn = blockIdx.y, b = blockIdx.z;
    const int tid = threadIdx.x, wid = tid >> 5, lane = tid & 31;
    const int u = wid >> 2, wi = wid & 3;
    const int g = lane >> 2, tg = lane & 3;
    const int q = lane >> 3, rr = lane & 7;

    // ---- W tile: 96 gc x 64 c halves via cp.async ----
#pragma unroll
    for (int r = 0; r < 3; r++) {
        const int i = r * 256 + tid;
        const int gcr = i >> 3, qq = i & 7;
        CP16(sb + wOff + (uint32_t)(gcr * WHST + qq * 8) * 2,
             g_Whf + (cn * 96 + gcr) * 64 + qq * 8);
    }
    CP_COMMIT();

    // ---- X tile: 64c x 256m fp32 -> fp16, [c][m] ----
#pragma unroll
    for (int r = 0; r < 16; r++) {
        const int i = r * 256 + tid;
        const int c = i >> 6, chunk = i & 63;
        const int nl = chunk >> 4, tq = chunk & 15;
        const float4 v = *(const float4*)(x + ((b * 64 + c) * 512 + n0 + nl) * 64 + tq * 4);
        union { __half2 h[2]; uint2 u2; } cv;
        cv.h[0] = __floats2half2_rn(v.x, v.y);
        cv.h[1] = __floats2half2_rn(v.z, v.w);
        *(uint2*)(Xh + c * XHST + nl * 64 + tq * 4) = cv.u2;
    }

    float acc[4][6][4];
#pragma unroll
    for (int mt = 0; mt < 4; mt++)
#pragma unroll
        for (int nt = 0; nt < 6; nt++)
#pragma unroll
            for (int r = 0; r < 4; r++) acc[mt][nt][r] = 0.f;

    CP_WAIT0();
    __syncthreads();

    // ---- mainloop: K=64 = 4 k16-steps ----
#pragma unroll
    for (int ks = 0; ks < 4; ks++) {
        uint32_t bf[3][4];
#pragma unroll
        for (int ntp = 0; ntp < 3; ntp++) {
            const int rowB = u * 48 + ntp * 16 + (q >> 1) * 8 + rr;   // gc'
            const int colB = ks * 16 + (q & 1) * 8;                   // c
            ldsm_x4(bf[ntp], sb + wOff + (uint32_t)(rowB * WHST + colB) * 2);
        }
#pragma unroll
        for (int mt = 0; mt < 4; mt++) {
            const int rowA = ks * 16 + (q >> 1) * 8 + rr;             // c
            const int colA = wi * 64 + mt * 16 + (q & 1) * 8;         // m
            uint32_t af[4];
            ldsm_x4t(af, sb + (uint32_t)(rowA * XHST + colA) * 2);
#pragma unroll
            for (int nt = 0; nt < 6; nt++)
                MMA_F16(acc[mt][nt], af[0], af[1], af[2], af[3],
                        bf[nt >> 1][(nt & 1) * 2], bf[nt >> 1][(nt & 1) * 2 + 1]);
        }
    }

    // ---- single-pass epilogue: Ss[oc'=96][m=256] transpose (reuses X+W) ----
    float* Ss = (float*)dsm;
    __syncthreads();                    // mainloop smem reads complete
#pragma unroll
    for (int mt = 0; mt < 4; mt++) {
        const int row = wi * 64 + mt * 16 + g;
#pragma unroll
        for (int nt = 0; nt < 6; nt++) {
            const int col = u * 48 + nt * 8 + tg * 2;
            Ss[col * SST + row]           = acc[mt][nt][0];
            Ss[(col + 1) * SST + row]     = acc[mt][nt][1];
            Ss[col * SST + row + 8]       = acc[mt][nt][2];
            Ss[(col + 1) * SST + row + 8] = acc[mt][nt][3];
        }
    }
    __syncthreads();
#pragma unroll
    for (int r = 0; r < 24; r++) {
        const int idx = r * 256 + tid;
        const int ocl = idx >> 6, mq = idx & 63;    // ocl 0..95
        float4 v = *(const float4*)(Ss + ocl * SST + mq * 4);
        const int gc = cn * 96 + ocl;
        const int grp = gc >> 6, oc = gc & 63;
        const int base = ((b * 64 + oc) * 512 + n0 + (mq >> 4)) * 64 + (mq & 15) * 4;
        if (grp == 0) {
            const float bv = __ldg(bias + oc);
            v.x += bv; v.y += bv; v.z += bv; v.w += bv;
            *(float4*)(out + base) = v;
        } else {
            __half* dst = (grp == 1) ? g_Z1h : g_Z2h;
            union { __half2 h[2]; uint2 u2; } cv;
            cv.h[0] = __floats2half2_rn(v.x, v.y);
            cv.h[1] = __floats2half2_rn(v.z, v.w);
            *(uint2*)(dst + base) = cv.u2;
        }
    }
}

// ---------------- kernel 2: out += norm@Z1 + norm2@Z2 (fp16 mma) -----------
// EXACT R8 configuration (measured ~248us, ~98% of legacy HMMA ceiling).
// CTA = 128i x 64t x 2oc, 256 thr / 8 warps, 2 CTAs/SM, Kc=32, 2-stage.
#define AHST 40                                // A smem stride (halves)
#define BHST 72                                // B smem stride (halves)
#define A_SEC   (128 * AHST * 2)               // 10240 per matrix
#define A_BYTES (2 * A_SEC)                    // 20480
#define B_TILE  (32 * BHST * 2)                // 4608
#define STAGE   (A_BYTES + 4 * B_TILE)         // 38912
#define NCHUNK  16

__global__ __launch_bounds__(256, 2) void k_spmm_mma(float* __restrict__ out) {
    extern __shared__ char sm[];
    const uint32_t sb = smem_u32(sm);
    const int tid = threadIdx.x, wid = tid >> 5, lane = tid & 31;
    const int ih = blockIdx.x, ocp = blockIdx.y, b = blockIdx.z;
    const int i0g = ih * 128, oc0 = ocp * 2;
    const int wi = wid & 1, u = wid >> 1;
    const int ocl = u >> 1, th = u & 1;
    const int g = lane >> 2, tg = lane & 3;
    const int q = lane >> 3, rr = lane & 7;

    const __half* zb[4];
    zb[0] = g_Z1h + (size_t)(b * 64 + oc0) * 32768;
    zb[1] = g_Z2h + (size_t)(b * 64 + oc0) * 32768;
    zb[2] = g_Z1h + (size_t)(b * 64 + oc0 + 1) * 32768;
    zb[3] = g_Z2h + (size_t)(b * 64 + oc0 + 1) * 32768;

    float acc[4][4][4];
#pragma unroll
    for (int mt = 0; mt < 4; mt++)
#pragma unroll
        for (int nt = 0; nt < 4; nt++)
#pragma unroll
            for (int r = 0; r < 4; r++) acc[mt][nt][r] = 0.f;

    auto load_stage = [&](int c) {
        const int j0 = c * 32;
        const uint32_t st = sb + (uint32_t)(c & 1) * STAGE;
#pragma unroll
        for (int r = 0; r < 4; r++) {                    // A: 2 x 128 x 32h
            const int i = r * 256 + tid;
            const int m = i >> 9, rem = i & 511;
            const int row = rem >> 2, qq = rem & 3;
            CP16(st + (uint32_t)(m * A_SEC + row * (AHST * 2) + qq * 16),
                 (m ? g_norm2h : g_normh) + (i0g + row) * 512 + j0 + qq * 8);
        }
#pragma unroll
        for (int r = 0; r < 4; r++) {                    // B: 4 x 32 x 64h
            const int i = r * 256 + tid;
            const int tb = i >> 8, rem = i & 255;
            const int j = rem >> 3, qq = rem & 7;
            CP16(st + (uint32_t)(A_BYTES + tb * B_TILE + j * (BHST * 2) + qq * 16),
                 zb[tb] + (j0 + j) * 64 + qq * 8);
        }
        CP_COMMIT();
    };

    load_stage(0);

    for (int c = 0; c < NCHUNK; c++) {
        if (c + 1 < NCHUNK) { load_stage(c + 1); CP_WAIT1(); }
        else                { CP_WAIT0(); }
        __syncthreads();

        const uint32_t aA = sb + (uint32_t)(c & 1) * STAGE;
        const uint32_t aB = aA + A_BYTES;

#pragma unroll
        for (int ks = 0; ks < 2; ks++) {
            uint32_t bf[2][2][4];
#pragma unroll
            for (int m = 0; m < 2; m++) {
#pragma unroll
                for (int ntp = 0; ntp < 2; ntp++) {
                    const int rowB = ks * 16 + (q & 1) * 8 + rr;
                    const int colB = th * 32 + ntp * 16 + (q >> 1) * 8;
                    ldsm_x4t(bf[m][ntp],
                             aB + (uint32_t)((ocl * 2 + m) * 32 * BHST + rowB * BHST + colB) * 2);
                }
            }
#pragma unroll
            for (int mt = 0; mt < 4; mt++) {
#pragma unroll
                for (int m = 0; m < 2; m++) {
                    const int rowA = wi * 64 + mt * 16 + (q & 1) * 8 + rr;
                    const int colA = ks * 16 + (q >> 1) * 8;
                    uint32_t af[4];
                    ldsm_x4(af, aA + (uint32_t)(m * 128 * AHST + rowA * AHST + colA) * 2);
#pragma unroll
                    for (int nt = 0; nt < 4; nt++)
                        MMA_F16(acc[mt][nt], af[0], af[1], af[2], af[3],
                                bf[m][nt >> 1][(nt & 1) * 2],
                                bf[m][nt >> 1][(nt & 1) * 2 + 1]);
                }
            }
        }
        __syncthreads();
    }

    // ---- epilogue: RMW into out (holds Z0 + bias, fp32) ----
    float* obase = out + (((size_t)(b * 64 + oc0 + ocl) * 512) + i0g + wi * 64) * 64;
#pragma unroll
    for (int mt = 0; mt < 4; mt++) {
#pragma unroll
        for (int nt = 0; nt < 4; nt++) {
            const int r0 = mt * 16 + g, t0 = th * 32 + nt * 8 + tg * 2;
            float2* p0 = (float2*)(obase + r0 * 64 + t0);
            float2 v0 = *p0;
            v0.x += acc[mt][nt][0]; v0.y += acc[mt][nt][1];
            *p0 = v0;
            float2* p1 = (float2*)(obase + (r0 + 8) * 64 + t0);
            float2 v1 = *p1;
            v1.x += acc[mt][nt][2]; v1.y += acc[mt][nt][3];
            *p1 = v1;
        }
    }
}

// ---------------------------------------------------------------------------
extern "C" void kernel_launch(void* const* d_in, const int* in_sizes, int n_in,
                              void* d_out, int out_size) {
    const float* x    = (const float*)d_in[0];   // (16, 64, 512, 64) f32
    const float* adj  = (const float*)d_in[1];   // (512, 512) f32
    const float* W    = (const float*)d_in[2];   // (64, 192) f32
    const float* bias = (const float*)d_in[3];   // (64,) f32
    float* out = (float*)d_out;                  // (16, 64, 512, 64) f32

    const int spmm_smem = 2 * STAGE;             // 77824
    cudaFuncSetAttribute(k_mix_f16, cudaFuncAttributeMaxDynamicSharedMemorySize, MIX_SMEM);
    cudaFuncSetAttribute(k_spmm_mma, cudaFuncAttributeMaxDynamicSharedMemorySize, spmm_smem);

    k_rownorm<<<N_, 256>>>(adj, W);
    k_norm2<<<dim3(32, 32), dim3(16, 16)>>>();
    k_mix_f16<<<dim3(128, 2, 16), 256, MIX_SMEM>>>(x, bias, out);
    k_spmm_mma<<<dim3(4, 32, 16), 256, spmm_smem>>>(out);
}

// round 14
// speedup vs baseline: 1.0487x; 1.0487x over previous
#include <cuda_runtime.h>
#include <cuda_fp16.h>
#include <cstdint>

#define B_  16
#define N_  512
#define T_  64
#define OC_ 64

// ---------------- scratch (device globals; no runtime allocation) ----------
__device__ __align__(16) float  g_norm  [N_ * N_];      // fp32 (k_norm2 input)
__device__ __align__(16) __half g_normh [N_ * N_];      // fp16 (spmm A)
__device__ __align__(16) __half g_norm2h[N_ * N_];      // fp16 (spmm A)
__device__ __align__(16) __half g_Z1h[B_ * OC_ * N_ * T_];
__device__ __align__(16) __half g_Z2h[B_ * OC_ * N_ * T_];
__device__ __align__(16) __half g_Whf[192 * 64];        // [gc][c] fp16

// ======================= helpers ===========================================
__device__ __forceinline__ uint32_t smem_u32(const void* p) {
    uint32_t a;
    asm("{ .reg .u64 t; cvta.to.shared.u64 t, %1; cvt.u32.u64 %0, t; }"
        : "=r"(a) : "l"(p));
    return a;
}

#define CP16(dst, src) \
    asm volatile("cp.async.cg.shared.global [%0], [%1], 16;" \
                 :: "r"(dst), "l"(src) : "memory")
#define CP_COMMIT()  asm volatile("cp.async.commit_group;" ::: "memory")
#define CP_WAIT1()   asm volatile("cp.async.wait_group 1;" ::: "memory")
#define CP_WAIT0()   asm volatile("cp.async.wait_group 0;" ::: "memory")

#define MMA_F16(c, a0, a1, a2, a3, b0, b1) \
    asm volatile("mma.sync.aligned.m16n8k16.row.col.f32.f16.f16.f32 " \
                 "{%0,%1,%2,%3}, {%4,%5,%6,%7}, {%8,%9}, {%0,%1,%2,%3};" \
                 : "+f"((c)[0]), "+f"((c)[1]), "+f"((c)[2]), "+f"((c)[3]) \
                 : "r"(a0), "r"(a1), "r"(a2), "r"(a3), "r"(b0), "r"(b1))

// fp16 accumulators: full-rate HMMA (f32-acc is half-rate)
#define MMA_F16ACC(c, a0, a1, a2, a3, b0, b1) \
    asm volatile("mma.sync.aligned.m16n8k16.row.col.f16.f16.f16.f16 " \
                 "{%0,%1}, {%2,%3,%4,%5}, {%6,%7}, {%0,%1};" \
                 : "+r"((c)[0]), "+r"((c)[1]) \
                 : "r"(a0), "r"(a1), "r"(a2), "r"(a3), "r"(b0), "r"(b1))

__device__ __forceinline__ void ldsm_x4(uint32_t* r, uint32_t addr) {
    asm volatile("ldmatrix.sync.aligned.m8n8.x4.shared.b16 {%0,%1,%2,%3}, [%4];"
                 : "=r"(r[0]), "=r"(r[1]), "=r"(r[2]), "=r"(r[3]) : "r"(addr));
}
__device__ __forceinline__ void ldsm_x4t(uint32_t* r, uint32_t addr) {
    asm volatile("ldmatrix.sync.aligned.m8n8.x4.trans.shared.b16 {%0,%1,%2,%3}, [%4];"
                 : "=r"(r[0]), "=r"(r[1]), "=r"(r[2]), "=r"(r[3]) : "r"(addr));
}

// ---------------- kernel 0a: row-normalized adjacency (+ fused W convert) --
__global__ void k_rownorm(const float* __restrict__ adj,
                          const float* __restrict__ W) {
    const int i = blockIdx.x;
    __shared__ float red[256];
    float s = 0.f;
    for (int j = threadIdx.x; j < N_; j += 256) s += adj[i * N_ + j];
    red[threadIdx.x] = s;
    __syncthreads();
    for (int off = 128; off > 0; off >>= 1) {
        if (threadIdx.x < off) red[threadIdx.x] += red[threadIdx.x + off];
        __syncthreads();
    }
    const float inv = 1.0f / (red[0] + 1e-6f);
    for (int j = threadIdx.x; j < N_; j += 256) {
        const float v = adj[i * N_ + j] * inv;
        g_norm [i * N_ + j] = v;
        g_normh[i * N_ + j] = __float2half_rn(v);
    }
    // fused W -> fp16 [gc][c]: blocks 0..47 cover 192*64 = 48*256 elements
    if (i < 48) {
        const int idx = i * 256 + threadIdx.x;      // idx = gc*64 + c
        const int gc = idx >> 6, c = idx & 63;
        const int grp = gc >> 6, oc = gc & 63;
        g_Whf[idx] = __float2half_rn(W[oc * 192 + grp * 64 + c]);
    }
}

// ---------------- kernel 0b: norm2 = norm @ norm (fp16 store) --------------
__global__ void k_norm2() {
    __shared__ float As[16][16];
    __shared__ float Bs[16][17];
    const int i = blockIdx.y * 16 + threadIdx.y;
    const int j = blockIdx.x * 16 + threadIdx.x;
    float acc = 0.f;
    for (int k0 = 0; k0 < N_; k0 += 16) {
        As[threadIdx.y][threadIdx.x] = g_norm[i * N_ + k0 + threadIdx.x];
        Bs[threadIdx.y][threadIdx.x] = g_norm[(k0 + threadIdx.y) * N_ + j];
        __syncthreads();
#pragma unroll
        for (int k = 0; k < 16; k++) acc += As[threadIdx.y][k] * Bs[k][threadIdx.x];
        __syncthreads();
    }
    g_norm2h[i * N_ + j] = __float2half_rn(acc);
}

// ---------------- kernel 1: channel mix via fp16 tensor cores ---------------
// EXACT R8 configuration (measured 97us). fp32 accum, two-pass epilogue.
#define XHST 264
#define WHST 72
#define SST  260
#define MIX_SMEM 49920

__global__ __launch_bounds__(256, 2) void k_mix_f16(const float* __restrict__ x,
                                                    const float* __restrict__ bias,
                                                    float* __restrict__ out) {
    extern __shared__ char dsm[];
    __half* Xh = (__half*)dsm;                       // [c=64][m=256]
    const uint32_t sb = smem_u32(dsm);
    const uint32_t wOff = 64 * XHST * 2;             // 33792
    const int n0 = blockIdx.x * 4, cn = blockIdx.y, b = blockIdx.z;
    const int tid = threadIdx.x, wid = tid >> 5, lane = tid & 31;
    const int u = wid >> 2, wi = wid & 3;
    const int g = lane >> 2, tg = lane & 3;
    const int q = lane >> 3, rr = lane & 7;

#pragma unroll
    for (int r = 0; r < 3; r++) {
        const int i = r * 256 + tid;
        const int gcr = i >> 3, qq = i & 7;
        CP16(sb + wOff + (uint32_t)(gcr * WHST + qq * 8) * 2,
             g_Whf + (cn * 96 + gcr) * 64 + qq * 8);
    }
    CP_COMMIT();

#pragma unroll
    for (int r = 0; r < 16; r++) {
        const int i = r * 256 + tid;
        const int c = i >> 6, chunk = i & 63;
        const int nl = chunk >> 4, tq = chunk & 15;
        const float4 v = *(const float4*)(x + ((b * 64 + c) * 512 + n0 + nl) * 64 + tq * 4);
        union { __half2 h[2]; uint2 u2; } cv;
        cv.h[0] = __floats2half2_rn(v.x, v.y);
        cv.h[1] = __floats2half2_rn(v.z, v.w);
        *(uint2*)(Xh + c * XHST + nl * 64 + tq * 4) = cv.u2;
    }

    float acc[4][6][4];
#pragma unroll
    for (int mt = 0; mt < 4; mt++)
#pragma unroll
        for (int nt = 0; nt < 6; nt++)
#pragma unroll
            for (int r = 0; r < 4; r++) acc[mt][nt][r] = 0.f;

    CP_WAIT0();
    __syncthreads();

#pragma unroll
    for (int ks = 0; ks < 4; ks++) {
        uint32_t bf[3][4];
#pragma unroll
        for (int ntp = 0; ntp < 3; ntp++) {
            const int rowB = u * 48 + ntp * 16 + (q >> 1) * 8 + rr;
            const int colB = ks * 16 + (q & 1) * 8;
            ldsm_x4(bf[ntp], sb + wOff + (uint32_t)(rowB * WHST + colB) * 2);
        }
#pragma unroll
        for (int mt = 0; mt < 4; mt++) {
            const int rowA = ks * 16 + (q >> 1) * 8 + rr;
            const int colA = wi * 64 + mt * 16 + (q & 1) * 8;
            uint32_t af[4];
            ldsm_x4t(af, sb + (uint32_t)(rowA * XHST + colA) * 2);
#pragma unroll
            for (int nt = 0; nt < 6; nt++)
                MMA_F16(acc[mt][nt], af[0], af[1], af[2], af[3],
                        bf[nt >> 1][(nt & 1) * 2], bf[nt >> 1][(nt & 1) * 2 + 1]);
        }
    }

    float* Ss = (float*)dsm;
#pragma unroll
    for (int up = 0; up < 2; up++) {
        __syncthreads();
        if (u == up) {
#pragma unroll
            for (int mt = 0; mt < 4; mt++) {
                const int row = wi * 64 + mt * 16 + g;
#pragma unroll
                for (int nt = 0; nt < 6; nt++) {
                    const int col = nt * 8 + tg * 2;
                    Ss[col * SST + row]           = acc[mt][nt][0];
                    Ss[(col + 1) * SST + row]     = acc[mt][nt][1];
                    Ss[col * SST + row + 8]       = acc[mt][nt][2];
                    Ss[(col + 1) * SST + row + 8] = acc[mt][nt][3];
                }
            }
        }
        __syncthreads();
#pragma unroll
        for (int r = 0; r < 12; r++) {
            const int idx = r * 256 + tid;
            const int ocl = idx >> 6, mq = idx & 63;
            float4 v = *(const float4*)(Ss + ocl * SST + mq * 4);
            const int gc = cn * 96 + up * 48 + ocl;
            const int grp = gc >> 6, oc = gc & 63;
            const int base = ((b * 64 + oc) * 512 + n0 + (mq >> 4)) * 64 + (mq & 15) * 4;
            if (grp == 0) {
                const float bv = __ldg(bias + oc);
                v.x += bv; v.y += bv; v.z += bv; v.w += bv;
                *(float4*)(out + base) = v;
            } else {
                __half* dst = (grp == 1) ? g_Z1h : g_Z2h;
                union { __half2 h[2]; uint2 u2; } cv;
                cv.h[0] = __floats2half2_rn(v.x, v.y);
                cv.h[1] = __floats2half2_rn(v.z, v.w);
                *(uint2*)(dst + base) = cv.u2;
            }
        }
    }
}

// ---------------- kernel 2: out += norm@Z1 + norm2@Z2 (fp16-acc mma) -------
// EXACT R8 structure; ONLY the mma instruction changed to fp16 accumulators.
// CTA = 128i x 64t x 2oc, 256 thr / 8 warps, 2 CTAs/SM, Kc=32, 2-stage.
#define AHST 40                                // A smem stride (halves)
#define BHST 72                                // B smem stride (halves)
#define A_SEC   (128 * AHST * 2)               // 10240 per matrix
#define A_BYTES (2 * A_SEC)                    // 20480
#define B_TILE  (32 * BHST * 2)                // 4608
#define STAGE   (A_BYTES + 4 * B_TILE)         // 38912
#define NCHUNK  16

__global__ __launch_bounds__(256, 2) void k_spmm_mma(float* __restrict__ out) {
    extern __shared__ char sm[];
    const uint32_t sb = smem_u32(sm);
    const int tid = threadIdx.x, wid = tid >> 5, lane = tid & 31;
    const int ih = blockIdx.x, ocp = blockIdx.y, b = blockIdx.z;
    const int i0g = ih * 128, oc0 = ocp * 2;
    const int wi = wid & 1, u = wid >> 1;
    const int ocl = u >> 1, th = u & 1;
    const int g = lane >> 2, tg = lane & 3;
    const int q = lane >> 3, rr = lane & 7;

    const __half* zb[4];
    zb[0] = g_Z1h + (size_t)(b * 64 + oc0) * 32768;
    zb[1] = g_Z2h + (size_t)(b * 64 + oc0) * 32768;
    zb[2] = g_Z1h + (size_t)(b * 64 + oc0 + 1) * 32768;
    zb[3] = g_Z2h + (size_t)(b * 64 + oc0 + 1) * 32768;

    uint32_t acc[4][4][2];
#pragma unroll
    for (int mt = 0; mt < 4; mt++)
#pragma unroll
        for (int nt = 0; nt < 4; nt++) { acc[mt][nt][0] = 0u; acc[mt][nt][1] = 0u; }

    auto load_stage = [&](int c) {
        const int j0 = c * 32;
        const uint32_t st = sb + (uint32_t)(c & 1) * STAGE;
#pragma unroll
        for (int r = 0; r < 4; r++) {                    // A: 2 x 128 x 32h
            const int i = r * 256 + tid;
            const int m = i >> 9, rem = i & 511;
            const int row = rem >> 2, qq = rem & 3;
            CP16(st + (uint32_t)(m * A_SEC + row * (AHST * 2) + qq * 16),
                 (m ? g_norm2h : g_normh) + (i0g + row) * 512 + j0 + qq * 8);
        }
#pragma unroll
        for (int r = 0; r < 4; r++) {                    // B: 4 x 32 x 64h
            const int i = r * 256 + tid;
            const int tb = i >> 8, rem = i & 255;
            const int j = rem >> 3, qq = rem & 7;
            CP16(st + (uint32_t)(A_BYTES + tb * B_TILE + j * (BHST * 2) + qq * 16),
                 zb[tb] + (j0 + j) * 64 + qq * 8);
        }
        CP_COMMIT();
    };

    load_stage(0);

    for (int c = 0; c < NCHUNK; c++) {
        if (c + 1 < NCHUNK) { load_stage(c + 1); CP_WAIT1(); }
        else                { CP_WAIT0(); }
        __syncthreads();

        const uint32_t aA = sb + (uint32_t)(c & 1) * STAGE;
        const uint32_t aB = aA + A_BYTES;

#pragma unroll
        for (int ks = 0; ks < 2; ks++) {
            uint32_t bf[2][2][4];
#pragma unroll
            for (int m = 0; m < 2; m++) {
#pragma unroll
                for (int ntp = 0; ntp < 2; ntp++) {
                    const int rowB = ks * 16 + (q & 1) * 8 + rr;
                    const int colB = th * 32 + ntp * 16 + (q >> 1) * 8;
                    ldsm_x4t(bf[m][ntp],
                             aB + (uint32_t)((ocl * 2 + m) * 32 * BHST + rowB * BHST + colB) * 2);
                }
            }
#pragma unroll
            for (int mt = 0; mt < 4; mt++) {
#pragma unroll
                for (int m = 0; m < 2; m++) {
                    const int rowA = wi * 64 + mt * 16 + (q & 1) * 8 + rr;
                    const int colA = ks * 16 + (q >> 1) * 8;
                    uint32_t af[4];
                    ldsm_x4(af, aA + (uint32_t)(m * 128 * AHST + rowA * AHST + colA) * 2);
#pragma unroll
                    for (int nt = 0; nt < 4; nt++)
                        MMA_F16ACC(acc[mt][nt], af[0], af[1], af[2], af[3],
                                   bf[m][nt >> 1][(nt & 1) * 2],
                                   bf[m][nt >> 1][(nt & 1) * 2 + 1]);
                }
            }
        }
        __syncthreads();
    }

    // ---- epilogue: fp16 partials -> fp32 RMW into out (holds Z0 + bias) ----
    float* obase = out + (((size_t)(b * 64 + oc0 + ocl) * 512) + i0g + wi * 64) * 64;
#pragma unroll
    for (int mt = 0; mt < 4; mt++) {
#pragma unroll
        for (int nt = 0; nt < 4; nt++) {
            const int r0 = mt * 16 + g, t0 = th * 32 + nt * 8 + tg * 2;
            union { uint32_t u2[2]; __half2 h[2]; } cv;
            cv.u2[0] = acc[mt][nt][0];
            cv.u2[1] = acc[mt][nt][1];
            const float2 lo = __half22float2(cv.h[0]);
            const float2 hi = __half22float2(cv.h[1]);
            float2* p0 = (float2*)(obase + r0 * 64 + t0);
            float2 v0 = *p0;
            v0.x += lo.x; v0.y += lo.y;
            *p0 = v0;
            float2* p1 = (float2*)(obase + (r0 + 8) * 64 + t0);
            float2 v1 = *p1;
            v1.x += hi.x; v1.y += hi.y;
            *p1 = v1;
        }
    }
}

// ---------------------------------------------------------------------------
extern "C" void kernel_launch(void* const* d_in, const int* in_sizes, int n_in,
                              void* d_out, int out_size) {
    const float* x    = (const float*)d_in[0];   // (16, 64, 512, 64) f32
    const float* adj  = (const float*)d_in[1];   // (512, 512) f32
    const float* W    = (const float*)d_in[2];   // (64, 192) f32
    const float* bias = (const float*)d_in[3];   // (64,) f32
    float* out = (float*)d_out;                  // (16, 64, 512, 64) f32

    const int spmm_smem = 2 * STAGE;             // 77824
    cudaFuncSetAttribute(k_mix_f16, cudaFuncAttributeMaxDynamicSharedMemorySize, MIX_SMEM);
    cudaFuncSetAttribute(k_spmm_mma, cudaFuncAttributeMaxDynamicSharedMemorySize, spmm_smem);

    k_rownorm<<<N_, 256>>>(adj, W);
    k_norm2<<<dim3(32, 32), dim3(16, 16)>>>();
    k_mix_f16<<<dim3(128, 2, 16), 256, MIX_SMEM>>>(x, bias, out);
    k_spmm_mma<<<dim3(4, 32, 16), 256, spmm_smem>>>(out);
}